// round 2
// baseline (speedup 1.0000x reference)
#include <cuda_runtime.h>
#include <cuda_fp16.h>
#include <cstdint>

// ---------------------------------------------------------------------------
// Problem constants
// ---------------------------------------------------------------------------
#define M_TOTAL 8192
#define N_TOTAL 4096
#define K_TOTAL 4096

#define TILE_M 128
#define TILE_N 128
#define TILE_K 64                    // K per pipeline stage
#define KTILES (K_TOTAL / TILE_K)    // 64
#define STAGES 4
#define THREADS 256
#define N_TILES (N_TOTAL / TILE_N)   // 32
#define M_TILES (M_TOTAL / TILE_M)   // 64
#define GROUP_M 8

#define STAGE_BYTES (2 * TILE_M * 128)          // A(16KB) + B(16KB) = 32KB
#define SMEM_DYN (STAGES * STAGE_BYTES)         // 128KB

// ---------------------------------------------------------------------------
// Scratch: pre-converted fp16 operands (device globals -> no allocations)
// ---------------------------------------------------------------------------
__device__ __half g_xh[(size_t)M_TOTAL * K_TOTAL];   // 67 MB
__device__ __half g_wh[(size_t)N_TOTAL * K_TOTAL];   // 33.5 MB

// ---------------------------------------------------------------------------
// Helpers
// ---------------------------------------------------------------------------
__device__ __forceinline__ uint32_t smem_u32(const void* p) {
    uint32_t a;
    asm("{ .reg .u64 t; cvta.to.shared.u64 t, %1; cvt.u32.u64 %0, t; }"
        : "=r"(a) : "l"(p));
    return a;
}

__device__ __forceinline__ uint32_t sw128(uint32_t off) {
    return off ^ ((off >> 3) & 0x70);
}

__device__ __forceinline__ void cp_async16(uint32_t dst, const void* src) {
    asm volatile("cp.async.cg.shared.global [%0], [%1], 16;"
                 :: "r"(dst), "l"(src) : "memory");
}
__device__ __forceinline__ void cp_commit() {
    asm volatile("cp.async.commit_group;" ::: "memory");
}
template <int N>
__device__ __forceinline__ void cp_wait() {
    asm volatile("cp.async.wait_group %0;" :: "n"(N) : "memory");
}

__device__ __forceinline__ void ldsm_x4(uint32_t& r0, uint32_t& r1, uint32_t& r2,
                                        uint32_t& r3, uint32_t addr) {
    asm volatile("ldmatrix.sync.aligned.m8n8.x4.shared.b16 {%0,%1,%2,%3}, [%4];"
                 : "=r"(r0), "=r"(r1), "=r"(r2), "=r"(r3) : "r"(addr));
}

__device__ __forceinline__ void mma16816(float& c0, float& c1, float& c2, float& c3,
                                         uint32_t a0, uint32_t a1, uint32_t a2,
                                         uint32_t a3, uint32_t b0, uint32_t b1) {
    asm volatile(
        "mma.sync.aligned.m16n8k16.row.col.f32.f16.f16.f32 "
        "{%0,%1,%2,%3}, {%4,%5,%6,%7}, {%8,%9}, {%0,%1,%2,%3};"
        : "+f"(c0), "+f"(c1), "+f"(c2), "+f"(c3)
        : "r"(a0), "r"(a1), "r"(a2), "r"(a3), "r"(b0), "r"(b1));
}

// ---------------------------------------------------------------------------
// Pass 1a: convert X (fp32) -> fp16
// ---------------------------------------------------------------------------
__global__ void __launch_bounds__(256) cvt_x_kernel(const float* __restrict__ x) {
    size_t i = (size_t)blockIdx.x * blockDim.x + threadIdx.x;   // chunk of 8 floats
    size_t n8 = (size_t)M_TOTAL * K_TOTAL / 8;
    if (i >= n8) return;
    const float4* s = reinterpret_cast<const float4*>(x) + 2 * i;
    float4 a = s[0], b = s[1];
    __half2 h0 = __floats2half2_rn(a.x, a.y);
    __half2 h1 = __floats2half2_rn(a.z, a.w);
    __half2 h2 = __floats2half2_rn(b.x, b.y);
    __half2 h3 = __floats2half2_rn(b.z, b.w);
    uint4 o;
    o.x = reinterpret_cast<uint32_t&>(h0);
    o.y = reinterpret_cast<uint32_t&>(h1);
    o.z = reinterpret_cast<uint32_t&>(h2);
    o.w = reinterpret_cast<uint32_t&>(h3);
    reinterpret_cast<uint4*>(g_xh)[i] = o;
}

// ---------------------------------------------------------------------------
// Pass 1b: dequantize W (int32 q * per-64-block scale) -> fp16
// flat element e has block id e/64; a chunk of 8 stays inside one block.
// ---------------------------------------------------------------------------
__global__ void __launch_bounds__(256) cvt_w_kernel(const int* __restrict__ qw,
                                                    const float* __restrict__ scales) {
    size_t i = (size_t)blockIdx.x * blockDim.x + threadIdx.x;   // chunk of 8 ints
    size_t n8 = (size_t)N_TOTAL * K_TOTAL / 8;
    if (i >= n8) return;
    float sc = __ldg(scales + (i >> 3));
    const int4* s = reinterpret_cast<const int4*>(qw) + 2 * i;
    int4 q0 = s[0], q1 = s[1];
    __half2 h0 = __floats2half2_rn((float)q0.x * sc, (float)q0.y * sc);
    __half2 h1 = __floats2half2_rn((float)q0.z * sc, (float)q0.w * sc);
    __half2 h2 = __floats2half2_rn((float)q1.x * sc, (float)q1.y * sc);
    __half2 h3 = __floats2half2_rn((float)q1.z * sc, (float)q1.w * sc);
    uint4 o;
    o.x = reinterpret_cast<uint32_t&>(h0);
    o.y = reinterpret_cast<uint32_t&>(h1);
    o.z = reinterpret_cast<uint32_t&>(h2);
    o.w = reinterpret_cast<uint32_t&>(h3);
    reinterpret_cast<uint4*>(g_wh)[i] = o;
}

// ---------------------------------------------------------------------------
// Pass 2: HMMA (mma.sync m16n8k16) GEMM, 128x128 tile, 4-stage cp.async pipe
//   A = g_xh [M,K] row-major (K-major), B = g_wh [N,K] row-major (K-major)
//   TN layout: both operands loaded with non-transposed ldmatrix.
// ---------------------------------------------------------------------------
__global__ void __launch_bounds__(THREADS) gemm_kernel(const float* __restrict__ bias,
                                                       float* __restrict__ out) {
    extern __shared__ char smem[];
    uint32_t sb = smem_u32(smem);

    int tid = threadIdx.x;
    int wid = tid >> 5;
    int lane = tid & 31;
    int warp_m = wid & 1;        // 2 warps in M
    int warp_n = wid >> 1;       // 4 warps in N

    // grouped tile rasterization for L2 reuse
    int bid = blockIdx.x;
    int group = bid / (GROUP_M * N_TILES);
    int rem = bid % (GROUP_M * N_TILES);
    int m_tile = group * GROUP_M + (rem % GROUP_M);
    int n_tile = rem / GROUP_M;
    int m_base = m_tile * TILE_M;
    int n_base = n_tile * TILE_N;

    const __half* Abase = g_xh + (size_t)m_base * K_TOTAL;
    const __half* Bbase = g_wh + (size_t)n_base * K_TOTAL;

    // per-thread cp.async chunk coords (chunk = 16B = 8 fp16)
    // 1024 chunks per operand per stage; thread handles 4 A + 4 B chunks
    int cr[4], cc[4];
#pragma unroll
    for (int i = 0; i < 4; ++i) {
        int t = tid + THREADS * i;
        cr[i] = t >> 3;          // row 0..127
        cc[i] = t & 7;           // 16B chunk in row, 0..7
    }

    float acc[4][4][4];
#pragma unroll
    for (int mi = 0; mi < 4; ++mi)
#pragma unroll
        for (int ni = 0; ni < 4; ++ni)
#pragma unroll
            for (int e = 0; e < 4; ++e) acc[mi][ni][e] = 0.0f;

    auto load_stage = [&](int kt, int buf) {
        uint32_t abase = sb + buf * STAGE_BYTES;
        uint32_t bbase = abase + TILE_M * 128;
        const __half* Ak = Abase + kt * TILE_K;
        const __half* Bk = Bbase + kt * TILE_K;
#pragma unroll
        for (int i = 0; i < 4; ++i) {
            uint32_t soff = sw128((uint32_t)(cr[i] * 128 + cc[i] * 16));
            cp_async16(abase + soff, Ak + (size_t)cr[i] * K_TOTAL + cc[i] * 8);
            cp_async16(bbase + soff, Bk + (size_t)cr[i] * K_TOTAL + cc[i] * 8);
        }
        cp_commit();
    };

    // prologue: stages 0..2
    load_stage(0, 0);
    load_stage(1, 1);
    load_stage(2, 2);

    // ldmatrix per-thread row/col-half (fixed across k-steps)
    int lrow = lane & 15;        // row within 16-row block
    int lhalf = lane >> 4;       // which 8-col (k) half

    for (int kt = 0; kt < KTILES; ++kt) {
        cp_wait<2>();
        __syncthreads();

        // prefetch stage kt+3 (overwrites buffer of stage kt-1, safe after sync)
        if (kt + 3 < KTILES) load_stage(kt + 3, (kt + 3) & (STAGES - 1));

        int buf = kt & (STAGES - 1);
        uint32_t abase = sb + buf * STAGE_BYTES;
        uint32_t bbase = abase + TILE_M * 128;

#pragma unroll
        for (int ks = 0; ks < 4; ++ks) {        // 4 x k16 per stage
            uint32_t a0[4], a1[4], a2[4], a3[4];
#pragma unroll
            for (int mi = 0; mi < 4; ++mi) {
                int row = warp_m * 64 + mi * 16 + lrow;
                uint32_t off = (uint32_t)(row * 128 + ks * 32 + lhalf * 16);
                ldsm_x4(a0[mi], a1[mi], a2[mi], a3[mi], abase + sw128(off));
            }
            uint32_t b0[4], b1[4];
#pragma unroll
            for (int nh = 0; nh < 2; ++nh) {
                int row = warp_n * 32 + nh * 16 + lrow;
                uint32_t off = (uint32_t)(row * 128 + ks * 32 + lhalf * 16);
                uint32_t r0, r1, r2, r3;
                ldsm_x4(r0, r1, r2, r3, bbase + sw128(off));
                b0[nh * 2 + 0] = r0; b1[nh * 2 + 0] = r2;   // n-block 0 of pair
                b0[nh * 2 + 1] = r1; b1[nh * 2 + 1] = r3;   // n-block 1 of pair
            }
#pragma unroll
            for (int mi = 0; mi < 4; ++mi)
#pragma unroll
                for (int ni = 0; ni < 4; ++ni)
                    mma16816(acc[mi][ni][0], acc[mi][ni][1],
                             acc[mi][ni][2], acc[mi][ni][3],
                             a0[mi], a1[mi], a2[mi], a3[mi],
                             b0[ni], b1[ni]);
        }
        __syncthreads();
    }

    // epilogue: bias add + store
    int qr = lane >> 2;          // 0..7 row within 8-row block
    int qc = (lane & 3) * 2;     // 0,2,4,6 col pair
#pragma unroll
    for (int mi = 0; mi < 4; ++mi) {
        int row0 = m_base + warp_m * 64 + mi * 16 + qr;
#pragma unroll
        for (int ni = 0; ni < 4; ++ni) {
            int col = n_base + warp_n * 32 + ni * 8 + qc;
            float bx = __ldg(bias + col);
            float by = __ldg(bias + col + 1);
            float2 v0 = make_float2(acc[mi][ni][0] + bx, acc[mi][ni][1] + by);
            float2 v1 = make_float2(acc[mi][ni][2] + bx, acc[mi][ni][3] + by);
            *reinterpret_cast<float2*>(out + (size_t)row0 * N_TOTAL + col) = v0;
            *reinterpret_cast<float2*>(out + (size_t)(row0 + 8) * N_TOTAL + col) = v1;
        }
    }
}

// ---------------------------------------------------------------------------
// kernel_launch
// ---------------------------------------------------------------------------
extern "C" void kernel_launch(void* const* d_in, const int* in_sizes, int n_in,
                              void* d_out, int out_size) {
    const float* x      = (const float*)d_in[0];
    const int*   qw     = (const int*)d_in[1];
    const float* scales = (const float*)d_in[2];
    const float* bias   = (const float*)d_in[3];
    float*       out    = (float*)d_out;

    cudaFuncSetAttribute(gemm_kernel, cudaFuncAttributeMaxDynamicSharedMemorySize, SMEM_DYN);

    int n8x = (int)((size_t)M_TOTAL * K_TOTAL / 8);   // 4,194,304
    int n8w = (int)((size_t)N_TOTAL * K_TOTAL / 8);   // 2,097,152
    cvt_x_kernel<<<(n8x + 255) / 256, 256>>>(x);
    cvt_w_kernel<<<(n8w + 255) / 256, 256>>>(qw, scales);
    gemm_kernel<<<M_TILES * N_TILES, THREADS, SMEM_DYN>>>(bias, out);
}

// round 3
// speedup vs baseline: 1.0767x; 1.0767x over previous
#include <cuda_runtime.h>
#include <cuda_fp16.h>
#include <cstdint>

// ---------------------------------------------------------------------------
// Problem constants
// ---------------------------------------------------------------------------
#define M_TOTAL 8192
#define N_TOTAL 4096
#define K_TOTAL 4096

#define TILE_M 256
#define TILE_N 128
#define TILE_K 64                    // K per pipeline stage
#define KTILES (K_TOTAL / TILE_K)    // 64
#define STAGES 4
#define THREADS 256
#define N_TILES (N_TOTAL / TILE_N)   // 32
#define M_TILES (M_TOTAL / TILE_M)   // 32
#define GROUP_M 8

#define STAGE_ROWS (TILE_M + TILE_N)            // 384 rows x 128B
#define STAGE_BYTES (STAGE_ROWS * 128)          // 48KB
#define SMEM_DYN (STAGES * STAGE_BYTES)         // 192KB

// ---------------------------------------------------------------------------
// Scratch: pre-converted fp16 operands (device globals -> no allocations)
// ---------------------------------------------------------------------------
__device__ __half g_xh[(size_t)M_TOTAL * K_TOTAL];   // 67 MB
__device__ __half g_wh[(size_t)N_TOTAL * K_TOTAL];   // 33.5 MB

// ---------------------------------------------------------------------------
// Helpers
// ---------------------------------------------------------------------------
__device__ __forceinline__ uint32_t smem_u32(const void* p) {
    uint32_t a;
    asm("{ .reg .u64 t; cvta.to.shared.u64 t, %1; cvt.u32.u64 %0, t; }"
        : "=r"(a) : "l"(p));
    return a;
}

__device__ __forceinline__ uint32_t sw128(uint32_t off) {
    return off ^ ((off >> 3) & 0x70);
}

__device__ __forceinline__ void cp_async16(uint32_t dst, const void* src) {
    asm volatile("cp.async.cg.shared.global [%0], [%1], 16;"
                 :: "r"(dst), "l"(src) : "memory");
}
__device__ __forceinline__ void cp_commit() {
    asm volatile("cp.async.commit_group;" ::: "memory");
}
template <int N>
__device__ __forceinline__ void cp_wait() {
    asm volatile("cp.async.wait_group %0;" :: "n"(N) : "memory");
}

__device__ __forceinline__ void ldsm_x4(uint32_t& r0, uint32_t& r1, uint32_t& r2,
                                        uint32_t& r3, uint32_t addr) {
    asm volatile("ldmatrix.sync.aligned.m8n8.x4.shared.b16 {%0,%1,%2,%3}, [%4];"
                 : "=r"(r0), "=r"(r1), "=r"(r2), "=r"(r3) : "r"(addr));
}

__device__ __forceinline__ void mma16816(float& c0, float& c1, float& c2, float& c3,
                                         uint32_t a0, uint32_t a1, uint32_t a2,
                                         uint32_t a3, uint32_t b0, uint32_t b1) {
    asm volatile(
        "mma.sync.aligned.m16n8k16.row.col.f32.f16.f16.f32 "
        "{%0,%1,%2,%3}, {%4,%5,%6,%7}, {%8,%9}, {%0,%1,%2,%3};"
        : "+f"(c0), "+f"(c1), "+f"(c2), "+f"(c3)
        : "r"(a0), "r"(a1), "r"(a2), "r"(a3), "r"(b0), "r"(b1));
}

// ---------------------------------------------------------------------------
// Pass 1a: convert X (fp32) -> fp16
// ---------------------------------------------------------------------------
__global__ void __launch_bounds__(256) cvt_x_kernel(const float* __restrict__ x) {
    size_t i = (size_t)blockIdx.x * blockDim.x + threadIdx.x;   // chunk of 8 floats
    size_t n8 = (size_t)M_TOTAL * K_TOTAL / 8;
    if (i >= n8) return;
    const float4* s = reinterpret_cast<const float4*>(x) + 2 * i;
    float4 a = s[0], b = s[1];
    __half2 h0 = __floats2half2_rn(a.x, a.y);
    __half2 h1 = __floats2half2_rn(a.z, a.w);
    __half2 h2 = __floats2half2_rn(b.x, b.y);
    __half2 h3 = __floats2half2_rn(b.z, b.w);
    uint4 o;
    o.x = reinterpret_cast<uint32_t&>(h0);
    o.y = reinterpret_cast<uint32_t&>(h1);
    o.z = reinterpret_cast<uint32_t&>(h2);
    o.w = reinterpret_cast<uint32_t&>(h3);
    reinterpret_cast<uint4*>(g_xh)[i] = o;
}

// ---------------------------------------------------------------------------
// Pass 1b: dequantize W (int32 q * per-64-block scale) -> fp16
// flat element e has block id e/64; a chunk of 8 stays inside one block.
// ---------------------------------------------------------------------------
__global__ void __launch_bounds__(256) cvt_w_kernel(const int* __restrict__ qw,
                                                    const float* __restrict__ scales) {
    size_t i = (size_t)blockIdx.x * blockDim.x + threadIdx.x;   // chunk of 8 ints
    size_t n8 = (size_t)N_TOTAL * K_TOTAL / 8;
    if (i >= n8) return;
    float sc = __ldg(scales + (i >> 3));
    const int4* s = reinterpret_cast<const int4*>(qw) + 2 * i;
    int4 q0 = s[0], q1 = s[1];
    __half2 h0 = __floats2half2_rn((float)q0.x * sc, (float)q0.y * sc);
    __half2 h1 = __floats2half2_rn((float)q0.z * sc, (float)q0.w * sc);
    __half2 h2 = __floats2half2_rn((float)q1.x * sc, (float)q1.y * sc);
    __half2 h3 = __floats2half2_rn((float)q1.z * sc, (float)q1.w * sc);
    uint4 o;
    o.x = reinterpret_cast<uint32_t&>(h0);
    o.y = reinterpret_cast<uint32_t&>(h1);
    o.z = reinterpret_cast<uint32_t&>(h2);
    o.w = reinterpret_cast<uint32_t&>(h3);
    reinterpret_cast<uint4*>(g_wh)[i] = o;
}

// ---------------------------------------------------------------------------
// Pass 2: HMMA GEMM, 256x128 CTA tile, warp tile 64x64, 4-stage cp.async
//   A = g_xh [M,K] K-major, B = g_wh [N,K] K-major (TN).
// ---------------------------------------------------------------------------
__global__ void __launch_bounds__(THREADS) gemm_kernel(const float* __restrict__ bias,
                                                       float* __restrict__ out) {
    extern __shared__ char smem[];
    uint32_t sb = smem_u32(smem);

    int tid = threadIdx.x;
    int wid = tid >> 5;
    int lane = tid & 31;
    int warp_m = wid & 3;        // 4 warps in M (64 rows each)
    int warp_n = wid >> 2;       // 2 warps in N (64 cols each)

    // grouped tile rasterization for L2 reuse
    int bid = blockIdx.x;
    int group = bid / (GROUP_M * N_TILES);
    int rem = bid % (GROUP_M * N_TILES);
    int m_tile = group * GROUP_M + (rem % GROUP_M);
    int n_tile = rem / GROUP_M;
    int m_base = m_tile * TILE_M;
    int n_base = n_tile * TILE_N;

    const __half* Abase = g_xh + (size_t)m_base * K_TOTAL;
    const __half* Bbase = g_wh + (size_t)n_base * K_TOTAL;

    // cp.async per-thread coords: chunk = 16B. Stage has 384 rows x 8 chunks.
    // i = 0..7 -> A rows (32*i + tr), i = 8..11 -> B rows (32*(i-8) + tr).
    int tr = tid >> 3;                 // 0..31
    int tc8 = (tid & 7) * 8;           // fp16 col offset
    uint32_t s0 = sw128((uint32_t)(tr * 128 + (tid & 7) * 16));  // swizzle invariant across row-groups

    float acc[4][8][4];
#pragma unroll
    for (int mi = 0; mi < 4; ++mi)
#pragma unroll
        for (int ni = 0; ni < 8; ++ni)
#pragma unroll
            for (int e = 0; e < 4; ++e) acc[mi][ni][e] = 0.0f;

    auto load_stage = [&](int kt, int buf) {
        uint32_t stage_base = sb + buf * STAGE_BYTES;
        const __half* Ak = Abase + kt * TILE_K;
        const __half* Bk = Bbase + kt * TILE_K;
#pragma unroll
        for (int i = 0; i < 8; ++i) {   // A: 256 rows
            cp_async16(stage_base + s0 + (uint32_t)i * 4096,
                       Ak + (size_t)(32 * i + tr) * K_TOTAL + tc8);
        }
        uint32_t bsm = stage_base + TILE_M * 128;
#pragma unroll
        for (int i = 0; i < 4; ++i) {   // B: 128 rows
            cp_async16(bsm + s0 + (uint32_t)i * 4096,
                       Bk + (size_t)(32 * i + tr) * K_TOTAL + tc8);
        }
        cp_commit();
    };

    // prologue
    load_stage(0, 0);
    load_stage(1, 1);
    load_stage(2, 2);

    int lrow = lane & 15;        // row within 16-row block
    int lhalf = lane >> 4;       // which 8-col (k) half

    for (int kt = 0; kt < KTILES; ++kt) {
        cp_wait<2>();
        __syncthreads();

        if (kt + 3 < KTILES) load_stage(kt + 3, (kt + 3) & (STAGES - 1));

        int buf = kt & (STAGES - 1);
        uint32_t abase = sb + buf * STAGE_BYTES;
        uint32_t bbase = abase + TILE_M * 128;

#pragma unroll
        for (int ks = 0; ks < 4; ++ks) {        // 4 x k16 per stage
            uint32_t a0[4], a1[4], a2[4], a3[4];
#pragma unroll
            for (int mi = 0; mi < 4; ++mi) {
                int row = warp_m * 64 + mi * 16 + lrow;
                uint32_t off = (uint32_t)(row * 128 + ks * 32 + lhalf * 16);
                ldsm_x4(a0[mi], a1[mi], a2[mi], a3[mi], abase + sw128(off));
            }
            uint32_t b0[8], b1[8];
#pragma unroll
            for (int nh = 0; nh < 4; ++nh) {
                int row = warp_n * 64 + nh * 16 + lrow;
                uint32_t off = (uint32_t)(row * 128 + ks * 32 + lhalf * 16);
                uint32_t r0, r1, r2, r3;
                ldsm_x4(r0, r1, r2, r3, bbase + sw128(off));
                b0[nh * 2 + 0] = r0; b1[nh * 2 + 0] = r2;
                b0[nh * 2 + 1] = r1; b1[nh * 2 + 1] = r3;
            }
#pragma unroll
            for (int mi = 0; mi < 4; ++mi)
#pragma unroll
                for (int ni = 0; ni < 8; ++ni)
                    mma16816(acc[mi][ni][0], acc[mi][ni][1],
                             acc[mi][ni][2], acc[mi][ni][3],
                             a0[mi], a1[mi], a2[mi], a3[mi],
                             b0[ni], b1[ni]);
        }
        __syncthreads();
    }

    // epilogue: bias add + store
    int qr = lane >> 2;          // 0..7
    int qc = (lane & 3) * 2;     // 0,2,4,6
#pragma unroll
    for (int mi = 0; mi < 4; ++mi) {
        int row0 = m_base + warp_m * 64 + mi * 16 + qr;
#pragma unroll
        for (int ni = 0; ni < 8; ++ni) {
            int col = n_base + warp_n * 64 + ni * 8 + qc;
            float bx = __ldg(bias + col);
            float by = __ldg(bias + col + 1);
            float2 v0 = make_float2(acc[mi][ni][0] + bx, acc[mi][ni][1] + by);
            float2 v1 = make_float2(acc[mi][ni][2] + bx, acc[mi][ni][3] + by);
            *reinterpret_cast<float2*>(out + (size_t)row0 * N_TOTAL + col) = v0;
            *reinterpret_cast<float2*>(out + (size_t)(row0 + 8) * N_TOTAL + col) = v1;
        }
    }
}

// ---------------------------------------------------------------------------
// kernel_launch
// ---------------------------------------------------------------------------
extern "C" void kernel_launch(void* const* d_in, const int* in_sizes, int n_in,
                              void* d_out, int out_size) {
    const float* x      = (const float*)d_in[0];
    const int*   qw     = (const int*)d_in[1];
    const float* scales = (const float*)d_in[2];
    const float* bias   = (const float*)d_in[3];
    float*       out    = (float*)d_out;

    cudaFuncSetAttribute(gemm_kernel, cudaFuncAttributeMaxDynamicSharedMemorySize, SMEM_DYN);

    int n8x = (int)((size_t)M_TOTAL * K_TOTAL / 8);   // 4,194,304
    int n8w = (int)((size_t)N_TOTAL * K_TOTAL / 8);   // 2,097,152
    cvt_x_kernel<<<(n8x + 255) / 256, 256>>>(x);
    cvt_w_kernel<<<(n8w + 255) / 256, 256>>>(qw, scales);
    gemm_kernel<<<M_TILES * N_TILES, THREADS, SMEM_DYN>>>(bias, out);
}